// round 10
// baseline (speedup 1.0000x reference)
#include <cuda_runtime.h>

#define NE 8
#define DIM 1024
#define NT 256
#define F4 (DIM / 4)
#define NG 36        // lower triangle of 8x8 Gram
#define RW 129       // 128 partials per value, +1 pad for bank-conflict-free column reads

__device__ __forceinline__ constexpr int tri(int i, int j) { return i * (i + 1) / 2 + j; }

__global__ __launch_bounds__(NT, 3) void gram_gs_kernel(
    const float* __restrict__ x, float* __restrict__ out) {
    const int t = threadIdx.x;
    const int warp = t >> 5;
    const int lane = t & 31;

    __shared__ float red[NG][RW];  // 18.6 KB
    __shared__ float gf_s[NG];

    const float4* __restrict__ xin =
        reinterpret_cast<const float4*>(x + (size_t)blockIdx.x * NE * DIM);
    float4* __restrict__ xout =
        reinterpret_cast<float4*>(out + (size_t)blockIdx.x * NE * DIM);

    // ---- Load all 8 expert slices (coalesced LDG.128, front-batched) ----
    float4 v[NE];
#pragma unroll
    for (int i = 0; i < NE; i++) v[i] = xin[i * F4 + t];

    // ---- Gram partials: 1-level shuffle, lanes 0-15 publish 128 partials/value ----
#pragma unroll
    for (int i = 0; i < NE; i++) {
#pragma unroll
        for (int j = 0; j <= i; j++) {
            float s = v[i].x * v[j].x + v[i].y * v[j].y +
                      v[i].z * v[j].z + v[i].w * v[j].w;
            s += __shfl_xor_sync(0xffffffffu, s, 16);
            if (lane < 16) red[tri(i, j)][warp * 16 + lane] = s;
        }
    }
    __syncthreads();

    // ---- Final reduce: threads 0..35 each sum 128 partials (conflict-free, 4-way ILP) ----
    if (t < NG) {
        float s0 = 0.f, s1 = 0.f, s2 = 0.f, s3 = 0.f;
#pragma unroll
        for (int m = 0; m < 128; m += 4) {
            s0 += red[t][m + 0];
            s1 += red[t][m + 1];
            s2 += red[t][m + 2];
            s3 += red[t][m + 3];
        }
        gf_s[t] = (s0 + s1) + (s2 + s3);
    }
    __syncthreads();

    // ---- Gram-Schmidt in coefficient space; W in regs, g read from smem (broadcast) ----
    float W[NG];
    {
        float inv = rsqrtf(gf_s[0]);
        W[0] = inv;
        float4 o;
        o.x = inv * v[0].x; o.y = inv * v[0].y;
        o.z = inv * v[0].z; o.w = inv * v[0].w;
        xout[t] = o;
    }

#pragma unroll
    for (int i = 1; i < NE; i++) {
        // Pull Gram row i from smem once (broadcast LDS).
        float gi[NE];
#pragma unroll
        for (int j = 0; j < NE; j++) {
            if (j <= i) gi[j] = gf_s[tri(i, j)];
        }
        // c_k = x_i . basis_k = sum_{j<=k} W[k][j] * G[i][j]
        float c[NE - 1];
#pragma unroll
        for (int k = 0; k < NE - 1; k++) {
            if (k < i) {
                float s = 0.f;
#pragma unroll
                for (int j = 0; j < NE - 1; j++) {
                    if (j <= k) s += W[tri(k, j)] * gi[j];
                }
                c[k] = s;
            }
        }
        // ||w||^2 = G_ii - sum c_k^2
        float n2 = gi[i];
#pragma unroll
        for (int k = 0; k < NE - 1; k++) {
            if (k < i) n2 -= c[k] * c[k];
        }
        float inv = rsqrtf(n2);
        // W[i][j] = -inv * sum_{k=j..i-1} c_k W[k][j];  W[i][i] = inv
#pragma unroll
        for (int j = 0; j < NE - 1; j++) {
            if (j < i) {
                float s = 0.f;
#pragma unroll
                for (int k = 0; k < NE - 1; k++) {
                    if (k >= j && k < i) s += c[k] * W[tri(k, j)];
                }
                W[tri(i, j)] = -inv * s;
            }
        }
        W[tri(i, i)] = inv;

        // Fused output row i = sum_{j<=i} W[i][j] * v_j
        float4 o = make_float4(0.f, 0.f, 0.f, 0.f);
#pragma unroll
        for (int j = 0; j < NE; j++) {
            if (j <= i) {
                float wj = W[tri(i, j)];
                o.x += wj * v[j].x;
                o.y += wj * v[j].y;
                o.z += wj * v[j].z;
                o.w += wj * v[j].w;
            }
        }
        xout[i * F4 + t] = o;
    }
}

extern "C" void kernel_launch(void* const* d_in, const int* in_sizes, int n_in,
                              void* d_out, int out_size) {
    const float* x = (const float*)d_in[0];
    float* out = (float*)d_out;
    const int batch = in_sizes[0] / (NE * DIM);  // 8192
    gram_gs_kernel<<<batch, NT>>>(x, out);
}

// round 11
// speedup vs baseline: 1.3758x; 1.3758x over previous
#include <cuda_runtime.h>

#define NE 8
#define DIM 1024
#define NT 256
#define F4 (DIM / 4)
#define NG 36     // lower triangle of 8x8 Gram
#define RW 129    // 128 partials + 1 pad -> conflict-free column sums

__device__ __forceinline__ constexpr int tri(int i, int j) { return i * (i + 1) / 2 + j; }

__global__ __launch_bounds__(NT, 4) void gram_chol_kernel(
    const float* __restrict__ x, float* __restrict__ out) {
    const int t = threadIdx.x;
    const int warp = t >> 5;
    const int lane = t & 31;

    __shared__ float red[NG][RW];  // 18.6 KB
    __shared__ float gf_s[NG];
    __shared__ float Ls[NG];       // Cholesky factor; diag slots hold 1/L_jj

    const float4* __restrict__ xin =
        reinterpret_cast<const float4*>(x + (size_t)blockIdx.x * NE * DIM);
    float4* __restrict__ xout =
        reinterpret_cast<float4*>(out + (size_t)blockIdx.x * NE * DIM);

    // ---- Load all 8 expert slices (coalesced LDG.128, streaming) ----
    float4 v[NE];
#pragma unroll
    for (int i = 0; i < NE; i++) v[i] = __ldcs(&xin[i * F4 + t]);

    // ---- Gram partials: 1-level shuffle; lanes 0-15 publish 128 partials/value ----
#pragma unroll
    for (int i = 0; i < NE; i++) {
#pragma unroll
        for (int j = 0; j <= i; j++) {
            float s = v[i].x * v[j].x + v[i].y * v[j].y +
                      v[i].z * v[j].z + v[i].w * v[j].w;
            s += __shfl_xor_sync(0xffffffffu, s, 16);
            if (lane < 16) red[tri(i, j)][warp * 16 + lane] = s;
        }
    }
    __syncthreads();

    // ---- Final reduce: threads 0..35 each sum 128 partials (4-way ILP) ----
    if (t < NG) {
        float s0 = 0.f, s1 = 0.f, s2 = 0.f, s3 = 0.f;
#pragma unroll
        for (int m = 0; m < 128; m += 4) {
            s0 += red[t][m + 0];
            s1 += red[t][m + 1];
            s2 += red[t][m + 2];
            s3 += red[t][m + 3];
        }
        gf_s[t] = (s0 + s1) + (s2 + s3);
    }
    __syncthreads();

    // ---- Warp 0: lane-parallel 8x8 Cholesky (lane i owns Gram row i) ----
    if (warp == 0) {
        float grow[NE];  // lane i: G[i][k]; lanes >=8 compute junk harmlessly
        const int li = lane;
#pragma unroll
        for (int k = 0; k < NE; k++) {
            const int r = (li < NE) ? li : 0;
            grow[k] = gf_s[(k <= r) ? tri(r, k) : tri(k, r)];
        }
#pragma unroll
        for (int j = 0; j < NE; j++) {
            const float diag = __shfl_sync(0xffffffffu, grow[j], j);
            const float inv = rsqrtf(diag);
            const float Lij = grow[j] * inv;  // lane i>=j: L[i][j]; lane j: L_jj
            if (li < NE && li >= j) Ls[tri(li, j)] = (li == j) ? inv : Lij;
#pragma unroll
            for (int k = 0; k < NE; k++) {
                if (k > j) {
                    const float Lkj = __shfl_sync(0xffffffffu, Lij, k);
                    grow[k] -= Lij * Lkj;
                }
            }
        }
    }
    __syncthreads();

    // ---- Column-oriented forward substitution: v <- L^-1 v, store as we go ----
#pragma unroll
    for (int j = 0; j < NE; j++) {
        const float invd = Ls[tri(j, j)];  // 1/L_jj (broadcast LDS)
        v[j].x *= invd; v[j].y *= invd; v[j].z *= invd; v[j].w *= invd;
        __stcs(&xout[j * F4 + t], v[j]);
#pragma unroll
        for (int i = 0; i < NE; i++) {
            if (i > j) {
                const float lij = Ls[tri(i, j)];
                v[i].x -= lij * v[j].x;
                v[i].y -= lij * v[j].y;
                v[i].z -= lij * v[j].z;
                v[i].w -= lij * v[j].w;
            }
        }
    }
}

extern "C" void kernel_launch(void* const* d_in, const int* in_sizes, int n_in,
                              void* d_out, int out_size) {
    const float* x = (const float*)d_in[0];
    float* out = (float*)d_out;
    const int batch = in_sizes[0] / (NE * DIM);  // 8192
    gram_chol_kernel<<<batch, NT>>>(x, out);
}